// round 10
// baseline (speedup 1.0000x reference)
#include <cuda_runtime.h>
#include <cuda_bf16.h>
#include <cstdint>

#define TT 16384
#define DD 2048
#define EE 64
#define KSEL 8
#define BR 128
#define KCH 32
#define NCH (DD / KCH)     // 64 chunks
#define EF 40              // experts 0..39 on fp32 pipe
#define EH 24              // experts 40..63 on tensor pipe
#define TAU 5e-5f

#define XSTR 80            // bf16 x row stride (bytes), 16B-aligned, ldmatrix-safe
#define BSTRB 80           // bf16 W row stride (bytes)
#define XB (BR * XSTR)     // 10240 B per x array per stage
#define WFB (KCH * EF * 4) // 5120 B fp32 W per stage (packed [32][40])
#define WHB (EH * BSTRB)   // 1920 B per bf16 W array per stage
#define OFF_XH 0
#define OFF_XM (2 * XB)                      // 20480
#define OFF_WF (4 * XB)                      // 40960
#define OFF_WH (4 * XB + 2 * WFB)            // 51200
#define OFF_WM (4 * XB + 2 * WFB + 2 * WHB)  // 55040
#define SMEM_TOTAL (4 * XB + 2 * WFB + 4 * WHB)  // 58880

typedef unsigned long long ull;

// ---- device scratch ----
__device__ float    g_wf[NCH * KCH * EF];   // [c][dl][40] fp32
__device__ uint16_t g_wbh[NCH * EH * KCH];  // [c][eh][dl] bf16 hi
__device__ uint16_t g_wbm[NCH * EH * KCH];  // bf16 residual
__device__ float g_cnt[EE];
__device__ float g_pn[EE];
__device__ int   g_nflag;
__device__ int   g_frows[TT];

static __device__ __forceinline__ uint32_t s2u(const void* p) {
    uint32_t a;
    asm("{ .reg .u64 t; cvta.to.shared.u64 t, %1; cvt.u32.u64 %0, t; }" : "=r"(a) : "l"(p));
    return a;
}

#define LDSM_X4(r0, r1, r2, r3, addr) \
    asm volatile("ldmatrix.sync.aligned.m8n8.x4.shared.b16 {%0,%1,%2,%3}, [%4];" \
                 : "=r"(r0), "=r"(r1), "=r"(r2), "=r"(r3) : "r"(addr))
#define LDSM_X2(r0, r1, addr) \
    asm volatile("ldmatrix.sync.aligned.m8n8.x2.shared.b16 {%0,%1}, [%2];" \
                 : "=r"(r0), "=r"(r1) : "r"(addr))
#define MMA_BF16(c, a0, a1, a2, a3, b0, b1) \
    asm volatile("mma.sync.aligned.m16n8k16.row.col.f32.bf16.bf16.f32 " \
                 "{%0,%1,%2,%3},{%4,%5,%6,%7},{%8,%9},{%0,%1,%2,%3};" \
                 : "+f"((c)[0]), "+f"((c)[1]), "+f"((c)[2]), "+f"((c)[3]) \
                 : "r"(a0), "r"(a1), "r"(a2), "r"(a3), "r"(b0), "r"(b1))

static __device__ __forceinline__ uint32_t pack_bf16(float a, float b) {
    __nv_bfloat162 h = __floats2bfloat162_rn(a, b);
    return *(uint32_t*)&h;
}

// ---------------------------------------------------------------------------
// prep: zero accumulators; W -> fp32 d-major (experts 0..39) + bf16 hi/res
// k-major tiles (experts 40..63), both chunked.
// ---------------------------------------------------------------------------
__global__ void prep_kernel(const float* __restrict__ W) {
    int idx = blockIdx.x * blockDim.x + threadIdx.x;
    if (idx == 0) g_nflag = 0;
    if (idx < EE)          g_cnt[idx] = 0.f;
    else if (idx < 2 * EE) g_pn[idx - EE] = 0.f;
    if (idx < DD * EE) {
        int e = idx >> 11;            // coalesced read of W[e][d]
        int d = idx & (DD - 1);
        int c = d >> 5, dl = d & 31;
        float v = W[idx];
        if (e < EF) {
            g_wf[c * (KCH * EF) + dl * EF + e] = v;
        } else {
            __nv_bfloat16 h = __float2bfloat16(v);
            __nv_bfloat16 m = __float2bfloat16(v - __bfloat162float(h));
            int eh = e - EF;
            g_wbh[c * (EH * KCH) + eh * KCH + dl] = *(uint16_t*)&h;
            g_wbm[c * (EH * KCH) + eh * KCH + dl] = *(uint16_t*)&m;
        }
    }
}

extern __shared__ char dsm[];

// ---------------------------------------------------------------------------
// router: 128 blocks x 256 threads, 128 rows/block.
// Dual-pipe: experts 0..39 via FFMA (fp32 pipe), 40..63 via 3-pass bf16 HMMA
// (tensor pipe) — concurrently, every warp. x staged once as bf16 (h, m);
// fp32 path reconstructs x = h + m (err ~2^-17, guarded by margin+patch).
// ---------------------------------------------------------------------------
__global__ void __launch_bounds__(256, 1) router_kernel(
    const float* __restrict__ x,
    const float* __restrict__ bias,
    float* __restrict__ out)
{
    __shared__ float bias_s[EE];
    __shared__ float cnt_s[EE];

    const int t = threadIdx.x, wid = t >> 5, lane = t & 31;
    const int r0 = blockIdx.x * BR;
    const uint32_t sb = s2u(dsm);

    if (t < EE) { bias_s[t] = bias[t]; cnt_s[t] = 0.f; }

    // ---- x staging: thread -> row t>>1, 16-float half t&1
    const int xrow = t >> 1, xh2 = t & 1;
    const float4* xg = (const float4*)(x + (size_t)(r0 + xrow) * DD + xh2 * 16);
    char* xsth = dsm + OFF_XH + xrow * XSTR + xh2 * 32;
    char* xstm = dsm + OFF_XM + xrow * XSTR + xh2 * 32;

    // ---- W staging: 512 x 16B pieces per chunk, 2 per thread
    //      p<320: Wf; 320..415: Wh; 416..511: Wm
    uint32_t wdst[2]; const char* wsrc[2];
    #pragma unroll
    for (int i = 0; i < 2; i++) {
        int p = t + 256 * i;
        if (p < 320) {
            wsrc[i] = (const char*)g_wf + p * 16;
            wdst[i] = sb + OFF_WF + p * 16;
        } else if (p < 416) {
            int j = p - 320, r = j >> 2, q = j & 3;
            wsrc[i] = (const char*)g_wbh + j * 16;
            wdst[i] = sb + OFF_WH + r * BSTRB + q * 16;
        } else {
            int j = p - 416, r = j >> 2, q = j & 3;
            wsrc[i] = (const char*)g_wbm + j * 16;
            wdst[i] = sb + OFF_WM + r * BSTRB + q * 16;
        }
    }

    // ---- ldmatrix lane addresses
    const int m0 = wid * 16;
    const uint32_t a_off  = (uint32_t)((m0 + (lane & 15)) * XSTR + (lane >> 4) * 16);
    const uint32_t b4_off = (uint32_t)(((lane & 7) + ((lane >> 4) << 3)) * BSTRB
                                       + ((lane >> 3) & 1) * 16);
    const uint32_t b2_off = (uint32_t)((16 + (lane & 7)) * BSTRB + ((lane >> 3) & 1) * 16);

    // ---- fp32 lane mapping: row m0+(lane&15), experts (lane>>4)*20 .. +19
    const int rowf = m0 + (lane & 15);
    const int eb   = (lane >> 4) * 20;

    float facc[20];
    #pragma unroll
    for (int j = 0; j < 20; j++) facc[j] = 0.f;
    float hacc[3][4];
    #pragma unroll
    for (int ti = 0; ti < 3; ti++)
        #pragma unroll
        for (int g = 0; g < 4; g++) hacc[ti][g] = 0.f;

    float4 rx[4];
    #pragma unroll
    for (int j = 0; j < 4; j++) rx[j] = xg[j];

    // prologue: W(0)
    #pragma unroll
    for (int i = 0; i < 2; i++)
        asm volatile("cp.async.cg.shared.global [%0], [%1], 16;"
                     :: "r"(wdst[i]), "l"(wsrc[i]));
    asm volatile("cp.async.commit_group;");

    const uint32_t WCH_F = KCH * EF * 4;   // gmem chunk strides
    const uint32_t WCH_B = EH * KCH * 2;

    for (int c = 0; c < NCH; c++) {
        const int b = c & 1;
        const uint32_t xo = b ? XB : 0u;
        const uint32_t wfo = b ? WFB : 0u;
        const uint32_t who = b ? WHB : 0u;

        // stage x(c): split to bf16 h/m, 2x STS.128 each
        {
            uint32_t hp[4], mp[4];
            #pragma unroll
            for (int j = 0; j < 4; j++) {
                float4 v = rx[j];
                hp[j] = pack_bf16(v.x, v.y) | 0u;
                uint32_t hq = pack_bf16(v.z, v.w);
                float fh0 = __bfloat162float(__float2bfloat16(v.x));
                float fh1 = __bfloat162float(__float2bfloat16(v.y));
                float fh2 = __bfloat162float(__float2bfloat16(v.z));
                float fh3 = __bfloat162float(__float2bfloat16(v.w));
                mp[j] = pack_bf16(v.x - fh0, v.y - fh1);
                uint32_t mq = pack_bf16(v.z - fh2, v.w - fh3);
                // store pair j as 8 bytes (two bf16x2)
                *(ull*)(xsth + xo + j * 8) = (ull)hp[j] | ((ull)hq << 32);
                *(ull*)(xstm + xo + j * 8) = (ull)mp[j] | ((ull)mq << 32);
            }
        }
        if (c + 1 < NCH) {
            #pragma unroll
            for (int j = 0; j < 4; j++) rx[j] = xg[(size_t)(c + 1) * 8 + j];
        }
        asm volatile("cp.async.wait_group 0;" ::: "memory");
        __syncthreads();
        if (c + 1 < NCH) {   // prefetch W(c+1) into other stage (safe: after sync)
            const uint32_t wo2f = (b ^ 1) ? WFB : 0u;
            const uint32_t wo2h = (b ^ 1) ? WHB : 0u;
            #pragma unroll
            for (int i = 0; i < 2; i++) {
                int p = t + 256 * i;
                uint32_t off = (p < 320) ? wo2f : wo2h;
                uint32_t gst = (p < 320) ? WCH_F : WCH_B;
                asm volatile("cp.async.cg.shared.global [%0], [%1], 16;"
                             :: "r"(wdst[i] + off), "l"(wsrc[i] + (size_t)(c + 1) * gst));
            }
            asm volatile("cp.async.commit_group;");
        }

        // ---- tensor pipe: 2 k16 steps, 3-pass bf16
        #pragma unroll
        for (int ks = 0; ks < 2; ks++) {
            uint32_t a0, a1, a2, a3, u0, u1, u2, u3;
            LDSM_X4(a0, a1, a2, a3, sb + OFF_XH + xo + a_off + ks * 32);
            LDSM_X4(u0, u1, u2, u3, sb + OFF_XM + xo + a_off + ks * 32);
            uint32_t bh0, bh1, bh2, bh3, bm0, bm1, bm2, bm3, ch0, ch1, cm0, cm1;
            LDSM_X4(bh0, bh1, bh2, bh3, sb + OFF_WH + who + b4_off + ks * 32);
            LDSM_X4(bm0, bm1, bm2, bm3, sb + OFF_WM + who + b4_off + ks * 32);
            LDSM_X2(ch0, ch1, sb + OFF_WH + who + b2_off + ks * 32);
            LDSM_X2(cm0, cm1, sb + OFF_WM + who + b2_off + ks * 32);
            MMA_BF16(hacc[0], a0, a1, a2, a3, bh0, bh1);
            MMA_BF16(hacc[0], a0, a1, a2, a3, bm0, bm1);
            MMA_BF16(hacc[0], u0, u1, u2, u3, bh0, bh1);
            MMA_BF16(hacc[1], a0, a1, a2, a3, bh2, bh3);
            MMA_BF16(hacc[1], a0, a1, a2, a3, bm2, bm3);
            MMA_BF16(hacc[1], u0, u1, u2, u3, bh2, bh3);
            MMA_BF16(hacc[2], a0, a1, a2, a3, ch0, ch1);
            MMA_BF16(hacc[2], a0, a1, a2, a3, cm0, cm1);
            MMA_BF16(hacc[2], u0, u1, u2, u3, ch0, ch1);
        }

        // ---- fp32 pipe: experts eb..eb+19, x reconstructed as h+m
        {
            const char*  xph = dsm + OFF_XH + xo + rowf * XSTR;
            const char*  xpm = dsm + OFF_XM + xo + rowf * XSTR;
            const float* wf  = (const float*)(dsm + OFF_WF + wfo);
            #pragma unroll
            for (int dg = 0; dg < 8; dg++) {
                uint2 hv = *(const uint2*)(xph + dg * 8);
                uint2 mv = *(const uint2*)(xpm + dg * 8);
                float2 h01 = __bfloat1622float2(*(__nv_bfloat162*)&hv.x);
                float2 h23 = __bfloat1622float2(*(__nv_bfloat162*)&hv.y);
                float2 m01 = __bfloat1622float2(*(__nv_bfloat162*)&mv.x);
                float2 m23 = __bfloat1622float2(*(__nv_bfloat162*)&mv.y);
                float xr[4] = { h01.x + m01.x, h01.y + m01.y,
                                h23.x + m23.x, h23.y + m23.y };
                #pragma unroll
                for (int dd = 0; dd < 4; dd++) {
                    const float4* wr = (const float4*)(wf + (dg * 4 + dd) * EF + eb);
                    float xv = xr[dd];
                    #pragma unroll
                    for (int q = 0; q < 5; q++) {
                        float4 w = wr[q];
                        facc[q * 4 + 0] = fmaf(xv, w.x, facc[q * 4 + 0]);
                        facc[q * 4 + 1] = fmaf(xv, w.y, facc[q * 4 + 1]);
                        facc[q * 4 + 2] = fmaf(xv, w.z, facc[q * 4 + 2]);
                        facc[q * 4 + 3] = fmaf(xv, w.w, facc[q * 4 + 3]);
                    }
                }
            }
        }
    }
    __syncthreads();   // all compute done before L overlay

    // ---- logits -> L[128][68] overlay
    float* Lf = (float*)dsm;
    {
        #pragma unroll
        for (int j = 0; j < 20; j++) Lf[rowf * 68 + eb + j] = facc[j];
        const int rr = m0 + (lane >> 2);
        const int cc = (lane & 3) * 2;
        #pragma unroll
        for (int ti = 0; ti < 3; ti++) {
            const int n0 = EF + ti * 8 + cc;
            Lf[rr * 68 + n0]           = hacc[ti][0];
            Lf[rr * 68 + n0 + 1]       = hacc[ti][1];
            Lf[(rr + 8) * 68 + n0]     = hacc[ti][2];
            Lf[(rr + 8) * 68 + n0 + 1] = hacc[ti][3];
        }
    }
    __syncthreads();

    // ---- per-row: sigmoid, top-9 margin test, finalize or flag
    if (t < BR) {
        float* Lr = Lf + t * 68;
        float ssum = 0.f;
        #pragma unroll
        for (int e = 0; e < EE; e++) {
            float a = 1.f / (1.f + expf(-Lr[e]));
            Lr[e] = a; ssum += a;
        }
        ull mask = 0ULL;
        float v9[9]; int i9[9];
        #pragma unroll
        for (int k = 0; k < 9; k++) {
            float best = -3.4e38f; int bi = 0;
            for (int e = 0; e < EE; e++) {
                if ((mask >> e) & 1ULL) continue;
                float v = Lr[e] + bias_s[e];
                if (v > best) { best = v; bi = e; }
            }
            mask |= 1ULL << bi; v9[k] = best; i9[k] = bi;
        }
        float ming = 3.4e38f;
        #pragma unroll
        for (int k = 0; k < 8; k++) ming = fminf(ming, v9[k] - v9[k + 1]);
        if (ming < TAU) {
            int s = atomicAdd(&g_nflag, 1);
            g_frows[s] = r0 + t;
            #pragma unroll
            for (int e = 0; e < EE; e++) Lr[e] = 0.f;   // exclude from P partials
        } else {
            float gsum = 0.f; float gv[KSEL];
            #pragma unroll
            for (int k = 0; k < KSEL; k++) {
                gv[k] = Lr[i9[k]]; gsum += gv[k];
                atomicAdd(&cnt_s[i9[k]], 1.f);
            }
            float inv = 1.f / (gsum + 1e-9f);
            size_t rg = (size_t)(r0 + t);
            #pragma unroll
            for (int k = 0; k < KSEL; k++) {
                out[rg * KSEL + k]                     = gv[k] * inv;
                out[(size_t)TT * KSEL + rg * KSEL + k] = (float)i9[k];
            }
            float pinv = 1.f / (ssum + 1e-9f);
            #pragma unroll
            for (int e = 0; e < EE; e++) Lr[e] *= pinv;
        }
    }
    __syncthreads();

    // ---- per-expert partial sums of affinity_norm
    {
        const int e = t & 63, seg = t >> 6;
        float s = 0.f;
        #pragma unroll
        for (int r = seg * 32; r < seg * 32 + 32; r++) s += Lf[r * 68 + e];
        atomicAdd(&g_pn[e], s);
    }
    if (t < EE) atomicAdd(&g_cnt[t], cnt_s[t]);
}

// ---------------------------------------------------------------------------
// patch: exact sequential-d fp32 recompute (R5/R7 numerics) for flagged rows
// ---------------------------------------------------------------------------
__global__ void __launch_bounds__(64) patch_kernel(
    const float* __restrict__ x, const float* __restrict__ W,
    const float* __restrict__ bias, float* __restrict__ out)
{
    __shared__ float xs[DD];
    __shared__ float aff[EE];
    __shared__ float pinv_s;
    const int e = threadIdx.x;
    const int nf = g_nflag;
    for (int i = blockIdx.x; i < nf; i += gridDim.x) {
        const int r = g_frows[i];
        for (int q = e; q < DD / 4; q += 64)
            ((float4*)xs)[q] = ((const float4*)(x + (size_t)r * DD))[q];
        __syncthreads();
        const float4* wr = (const float4*)(W + (size_t)e * DD);
        float acc = 0.f;
        #pragma unroll 4
        for (int q = 0; q < DD / 4; q++) {
            float4 w = wr[q];
            acc = fmaf(xs[4 * q + 0], w.x, acc);
            acc = fmaf(xs[4 * q + 1], w.y, acc);
            acc = fmaf(xs[4 * q + 2], w.z, acc);
            acc = fmaf(xs[4 * q + 3], w.w, acc);
        }
        aff[e] = 1.f / (1.f + expf(-acc));
        __syncthreads();
        if (e == 0) {
            float ssum = 0.f;
            for (int k = 0; k < EE; k++) ssum += aff[k];
            ull mask = 0ULL; float gsum = 0.f;
            float gv[KSEL]; int gi[KSEL];
            for (int k = 0; k < KSEL; k++) {
                float best = -3.4e38f; int bi = 0;
                for (int j = 0; j < EE; j++) {
                    if ((mask >> j) & 1ULL) continue;
                    float v = aff[j] + bias[j];
                    if (v > best) { best = v; bi = j; }
                }
                mask |= 1ULL << bi; gi[k] = bi;
                float a = aff[bi]; gv[k] = a; gsum += a;
                atomicAdd(&g_cnt[bi], 1.f);
            }
            float inv = 1.f / (gsum + 1e-9f);
            for (int k = 0; k < KSEL; k++) {
                out[(size_t)r * KSEL + k]                     = gv[k] * inv;
                out[(size_t)TT * KSEL + (size_t)r * KSEL + k] = (float)gi[k];
            }
            pinv_s = 1.f / (ssum + 1e-9f);
        }
        __syncthreads();
        atomicAdd(&g_pn[e], aff[e] * pinv_s);
        __syncthreads();
    }
}

// ---------------------------------------------------------------------------
__global__ void finalize_kernel(float* __restrict__ out) {
    __shared__ float red[EE];
    const int e = threadIdx.x;
    red[e] = g_cnt[e] * g_pn[e];
    __syncthreads();
    if (e == 0) {
        float s = 0.f;
        for (int i = 0; i < EE; i++) s += red[i];
        double loss = (double)s * 1e-4 * 64.0 / (8.0 * 16384.0) / 16384.0;
        out[(size_t)2 * TT * KSEL] = (float)loss;
    }
}

// ---------------------------------------------------------------------------
extern "C" void kernel_launch(void* const* d_in, const int* in_sizes, int n_in,
                              void* d_out, int out_size) {
    const float* x    = (const float*)d_in[0];
    const float* W    = (const float*)d_in[1];
    const float* bias = (const float*)d_in[2];
    float* out = (float*)d_out;

    static bool attr_done = false;
    if (!attr_done) {
        cudaFuncSetAttribute(router_kernel,
                             cudaFuncAttributeMaxDynamicSharedMemorySize, SMEM_TOTAL);
        attr_done = true;
    }

    prep_kernel<<<512, 256>>>(W);
    router_kernel<<<TT / BR, 256, SMEM_TOTAL>>>(x, bias, out);
    patch_kernel<<<512, 64>>>(x, W, bias, out);
    finalize_kernel<<<1, 64>>>(out);
}

// round 11
// speedup vs baseline: 1.5808x; 1.5808x over previous
#include <cuda_runtime.h>
#include <cuda_bf16.h>
#include <cstdint>

#define TT 16384
#define DD 2048
#define EE 64
#define KSEL 8
#define BR 128
#define KCH 32
#define NCH (DD / KCH)    // 64 chunks
#define TAU 5e-5f

#define ASTR 80           // A smem row stride (bytes), 16B-aligned, conflict-free
#define BSTR 80
#define ABUF (BR * ASTR)  // 10240 B per stage
#define BBUF (EE * BSTR)  // 5120 B per stage
#define OFF_AH 0
#define OFF_AM (2 * ABUF)             // 20480
#define OFF_BH (4 * ABUF)             // 40960
#define OFF_BM (4 * ABUF + 2 * BBUF)  // 51200
#define SMEM_TOTAL (4 * ABUF + 4 * BBUF)  // 61440

typedef unsigned long long ull;

// ---- device scratch ----
__device__ uint16_t g_wh[EE * DD];   // bf16 hi part of W, [e][d]
__device__ uint16_t g_wm[EE * DD];   // bf16 residual part
__device__ float g_cnt[EE];
__device__ float g_pn[EE];
__device__ int   g_nflag;
__device__ int   g_frows[TT];

static __device__ __forceinline__ uint32_t s2u(const void* p) {
    uint32_t a;
    asm("{ .reg .u64 t; cvta.to.shared.u64 t, %1; cvt.u32.u64 %0, t; }" : "=r"(a) : "l"(p));
    return a;
}

#define LDSM_X4(r0, r1, r2, r3, addr) \
    asm volatile("ldmatrix.sync.aligned.m8n8.x4.shared.b16 {%0,%1,%2,%3}, [%4];" \
                 : "=r"(r0), "=r"(r1), "=r"(r2), "=r"(r3) : "r"(addr))

#define MMA_BF16(c, a0, a1, a2, a3, b0, b1) \
    asm volatile("mma.sync.aligned.m16n8k16.row.col.f32.bf16.bf16.f32 " \
                 "{%0,%1,%2,%3},{%4,%5,%6,%7},{%8,%9},{%0,%1,%2,%3};" \
                 : "+f"((c)[0]), "+f"((c)[1]), "+f"((c)[2]), "+f"((c)[3]) \
                 : "r"(a0), "r"(a1), "r"(a2), "r"(a3), "r"(b0), "r"(b1))

static __device__ __forceinline__ uint32_t pack_bf16(float a, float b) {
    __nv_bfloat162 h = __floats2bfloat162_rn(a, b);
    return *(uint32_t*)&h;
}

// ---------------------------------------------------------------------------
// prep: zero accumulators; split W into bf16 hi/residual, [e][d] row-major
// ---------------------------------------------------------------------------
__global__ void prep_kernel(const float* __restrict__ W) {
    int idx = blockIdx.x * blockDim.x + threadIdx.x;
    if (idx == 0) g_nflag = 0;
    if (idx < EE)          g_cnt[idx] = 0.f;
    else if (idx < 2 * EE) g_pn[idx - EE] = 0.f;
    if (idx < DD * EE) {
        float v = W[idx];
        __nv_bfloat16 h = __float2bfloat16(v);
        __nv_bfloat16 m = __float2bfloat16(v - __bfloat162float(h));
        g_wh[idx] = *(uint16_t*)&h;
        g_wm[idx] = *(uint16_t*)&m;
    }
}

extern __shared__ char dsm[];

// ---------------------------------------------------------------------------
// router: 128 blocks x 256 threads, 128 rows/block, HMMA bf16 3-pass split.
// R11: W prefetched one chunk ahead; accumulators split into 2 independent
// sets with pass-major MMA order (no RAW-on-C stalls).
// ---------------------------------------------------------------------------
__global__ void __launch_bounds__(256, 1) router_kernel(
    const float* __restrict__ x,
    const float* __restrict__ bias,
    float* __restrict__ out)
{
    __shared__ float bias_s[EE];
    __shared__ float cnt_s[EE];

    const int t = threadIdx.x, wid = t >> 5, lane = t & 31;
    const int r0 = blockIdx.x * BR;
    const uint32_t sb = s2u(dsm);

    if (t < EE) { bias_s[t] = bias[t]; cnt_s[t] = 0.f; }

    // ---- staging maps (identical to R9)
    const int ar = t >> 1, ah2 = t & 1;              // x: row, 16-float half
    const float4* xg = (const float4*)(x + (size_t)(r0 + ar) * DD + ah2 * 16);
    char* asth = dsm + OFF_AH + ar * ASTR + ah2 * 32;
    char* astm = dsm + OFF_AM + ar * ASTR + ah2 * 32;

    const int brr = t >> 2, bq = t & 3;              // W: row, 16B quarter
    const char* bsh = (const char*)g_wh + ((size_t)brr * DD) * 2 + bq * 16;
    const char* bsm = (const char*)g_wm + ((size_t)brr * DD) * 2 + bq * 16;
    const uint32_t bdh = sb + OFF_BH + brr * BSTR + bq * 16;
    const uint32_t bdm = sb + OFF_BM + brr * BSTR + bq * 16;

    // ---- ldmatrix lane addresses (identical to R9)
    const int m0 = wid * 16;
    const uint32_t a_off = (uint32_t)((m0 + (lane & 15)) * ASTR + (lane >> 4) * 16);
    const uint32_t b_off = (uint32_t)(((lane & 7) + ((lane >> 4) << 3)) * BSTR
                                      + ((lane >> 3) & 1) * 16);

    float acc0[8][4], acc1[8][4];
    #pragma unroll
    for (int i = 0; i < 8; i++)
        #pragma unroll
        for (int g = 0; g < 4; g++) { acc0[i][g] = 0.f; acc1[i][g] = 0.f; }

    float4 rx[4];
    #pragma unroll
    for (int j = 0; j < 4; j++) rx[j] = xg[j];

    // ---- prologue: W(0) in flight
    asm volatile("cp.async.cg.shared.global [%0], [%1], 16;" :: "r"(bdh), "l"(bsh));
    asm volatile("cp.async.cg.shared.global [%0], [%1], 16;" :: "r"(bdm), "l"(bsm));
    asm volatile("cp.async.commit_group;");

    for (int c = 0; c < NCH; c++) {
        const int b = c & 1;

        // stage x(c): split to bf16 h/m, STS.64 per float4
        #pragma unroll
        for (int j = 0; j < 4; j++) {
            float4 v = rx[j];
            float fh0 = __bfloat162float(__float2bfloat16(v.x));
            float fh1 = __bfloat162float(__float2bfloat16(v.y));
            float fh2 = __bfloat162float(__float2bfloat16(v.z));
            float fh3 = __bfloat162float(__float2bfloat16(v.w));
            uint32_t hlo = pack_bf16(v.x, v.y), hhi = pack_bf16(v.z, v.w);
            uint32_t mlo = pack_bf16(v.x - fh0, v.y - fh1);
            uint32_t mhi = pack_bf16(v.z - fh2, v.w - fh3);
            *(ull*)(asth + b * ABUF + j * 8) = (ull)hlo | ((ull)hhi << 32);
            *(ull*)(astm + b * ABUF + j * 8) = (ull)mlo | ((ull)mhi << 32);
        }

        if (c + 1 < NCH) {
            // prefetch W(c+1) into the other stage (safe: that stage was
            // consumed by compute(c-1), which ended before last sync)
            const uint32_t wo = (b ^ 1) ? BBUF : 0u;
            const char* s0 = bsh + (size_t)(c + 1) * KCH * 2;
            const char* s1 = bsm + (size_t)(c + 1) * KCH * 2;
            asm volatile("cp.async.cg.shared.global [%0], [%1], 16;"
                         :: "r"(bdh + wo), "l"(s0));
            asm volatile("cp.async.cg.shared.global [%0], [%1], 16;"
                         :: "r"(bdm + wo), "l"(s1));
            asm volatile("cp.async.commit_group;");
            // prefetch x(c+1) into registers
            #pragma unroll
            for (int j = 0; j < 4; j++) rx[j] = xg[(size_t)(c + 1) * (KCH / 4) + j];
            asm volatile("cp.async.wait_group 1;" ::: "memory");   // W(c) ready
        } else {
            asm volatile("cp.async.wait_group 0;" ::: "memory");
        }
        __syncthreads();

        // ---- compute chunk c: 2 k16 steps, pass-major, split accumulators
        #pragma unroll
        for (int ks = 0; ks < 2; ks++) {
            const uint32_t ao = sb + b * ABUF + a_off + ks * 32;
            uint32_t ah0, ah1, ah2r, ah3, am0, am1, am2, am3;
            LDSM_X4(ah0, ah1, ah2r, ah3, ao + OFF_AH);
            LDSM_X4(am0, am1, am2, am3, ao + OFF_AM);
            uint32_t bh[4][4], bm[4][4];
            #pragma unroll
            for (int g = 0; g < 4; g++) {
                const uint32_t bo = sb + b * BBUF + b_off + g * (16 * BSTR) + ks * 32;
                LDSM_X4(bh[g][0], bh[g][1], bh[g][2], bh[g][3], bo + OFF_BH);
                LDSM_X4(bm[g][0], bm[g][1], bm[g][2], bm[g][3], bo + OFF_BM);
            }
            // pass hh -> acc0 (8 independent MMAs)
            #pragma unroll
            for (int g = 0; g < 4; g++) {
                MMA_BF16(acc0[2 * g],     ah0, ah1, ah2r, ah3, bh[g][0], bh[g][1]);
                MMA_BF16(acc0[2 * g + 1], ah0, ah1, ah2r, ah3, bh[g][2], bh[g][3]);
            }
            // pass hm -> acc1
            #pragma unroll
            for (int g = 0; g < 4; g++) {
                MMA_BF16(acc1[2 * g],     ah0, ah1, ah2r, ah3, bm[g][0], bm[g][1]);
                MMA_BF16(acc1[2 * g + 1], ah0, ah1, ah2r, ah3, bm[g][2], bm[g][3]);
            }
            // pass mh -> acc1 (same acc as hm, but 8 MMAs apart)
            #pragma unroll
            for (int g = 0; g < 4; g++) {
                MMA_BF16(acc1[2 * g],     am0, am1, am2, am3, bh[g][0], bh[g][1]);
                MMA_BF16(acc1[2 * g + 1], am0, am1, am2, am3, bh[g][2], bh[g][3]);
            }
        }
        __syncthreads();   // compute(c) done before next store/prefetch reuse
    }

    // ---- logits -> L[128][68] overlay
    float* Lf = (float*)dsm;
    {
        const int rr = m0 + (lane >> 2);
        const int cc = (lane & 3) * 2;
        #pragma unroll
        for (int ti = 0; ti < 8; ti++) {
            const int n0 = ti * 8 + cc;
            Lf[rr * 68 + n0]           = acc0[ti][0] + acc1[ti][0];
            Lf[rr * 68 + n0 + 1]       = acc0[ti][1] + acc1[ti][1];
            Lf[(rr + 8) * 68 + n0]     = acc0[ti][2] + acc1[ti][2];
            Lf[(rr + 8) * 68 + n0 + 1] = acc0[ti][3] + acc1[ti][3];
        }
    }
    __syncthreads();

    // ---- per-row: sigmoid, top-9 margin test, finalize or flag
    if (t < BR) {
        float* Lr = Lf + t * 68;
        float ssum = 0.f;
        #pragma unroll
        for (int e = 0; e < EE; e++) {
            float a = 1.f / (1.f + expf(-Lr[e]));
            Lr[e] = a; ssum += a;
        }
        ull mask = 0ULL;
        float v9[9]; int i9[9];
        #pragma unroll
        for (int k = 0; k < 9; k++) {
            float best = -3.4e38f; int bi = 0;
            for (int e = 0; e < EE; e++) {
                if ((mask >> e) & 1ULL) continue;
                float v = Lr[e] + bias_s[e];
                if (v > best) { best = v; bi = e; }
            }
            mask |= 1ULL << bi; v9[k] = best; i9[k] = bi;
        }
        float ming = 3.4e38f;
        #pragma unroll
        for (int k = 0; k < 8; k++) ming = fminf(ming, v9[k] - v9[k + 1]);
        if (ming < TAU) {
            int s = atomicAdd(&g_nflag, 1);
            g_frows[s] = r0 + t;
            #pragma unroll
            for (int e = 0; e < EE; e++) Lr[e] = 0.f;   // exclude from P partials
        } else {
            float gsum = 0.f; float gv[KSEL];
            #pragma unroll
            for (int k = 0; k < KSEL; k++) {
                gv[k] = Lr[i9[k]]; gsum += gv[k];
                atomicAdd(&cnt_s[i9[k]], 1.f);
            }
            float inv = 1.f / (gsum + 1e-9f);
            size_t rg = (size_t)(r0 + t);
            #pragma unroll
            for (int k = 0; k < KSEL; k++) {
                out[rg * KSEL + k]                     = gv[k] * inv;
                out[(size_t)TT * KSEL + rg * KSEL + k] = (float)i9[k];
            }
            float pinv = 1.f / (ssum + 1e-9f);
            #pragma unroll
            for (int e = 0; e < EE; e++) Lr[e] *= pinv;
        }
    }
    __syncthreads();

    // ---- per-expert partial sums of affinity_norm
    {
        const int e = t & 63, seg = t >> 6;
        float s = 0.f;
        #pragma unroll
        for (int r = seg * 32; r < seg * 32 + 32; r++) s += Lf[r * 68 + e];
        atomicAdd(&g_pn[e], s);
    }
    if (t < EE) atomicAdd(&g_cnt[t], cnt_s[t]);
}

// ---------------------------------------------------------------------------
// patch: exact sequential-d fp32 recompute (R5/R7 numerics) for flagged rows
// ---------------------------------------------------------------------------
__global__ void __launch_bounds__(64) patch_kernel(
    const float* __restrict__ x, const float* __restrict__ W,
    const float* __restrict__ bias, float* __restrict__ out)
{
    __shared__ float xs[DD];
    __shared__ float aff[EE];
    __shared__ float pinv_s;
    const int e = threadIdx.x;
    const int nf = g_nflag;
    for (int i = blockIdx.x; i < nf; i += gridDim.x) {
        const int r = g_frows[i];
        for (int q = e; q < DD / 4; q += 64)
            ((float4*)xs)[q] = ((const float4*)(x + (size_t)r * DD))[q];
        __syncthreads();
        const float4* wr = (const float4*)(W + (size_t)e * DD);
        float acc = 0.f;
        #pragma unroll 4
        for (int q = 0; q < DD / 4; q++) {
            float4 w = wr[q];
            acc = fmaf(xs[4 * q + 0], w.x, acc);
            acc = fmaf(xs[4 * q + 1], w.y, acc);
            acc = fmaf(xs[4 * q + 2], w.z, acc);
            acc = fmaf(xs[4 * q + 3], w.w, acc);
        }
        aff[e] = 1.f / (1.f + expf(-acc));
        __syncthreads();
        if (e == 0) {
            float ssum = 0.f;
            for (int k = 0; k < EE; k++) ssum += aff[k];
            ull mask = 0ULL; float gsum = 0.f;
            float gv[KSEL]; int gi[KSEL];
            for (int k = 0; k < KSEL; k++) {
                float best = -3.4e38f; int bi = 0;
                for (int j = 0; j < EE; j++) {
                    if ((mask >> j) & 1ULL) continue;
                    float v = aff[j] + bias[j];
                    if (v > best) { best = v; bi = j; }
                }
                mask |= 1ULL << bi; gi[k] = bi;
                float a = aff[bi]; gv[k] = a; gsum += a;
                atomicAdd(&g_cnt[bi], 1.f);
            }
            float inv = 1.f / (gsum + 1e-9f);
            for (int k = 0; k < KSEL; k++) {
                out[(size_t)r * KSEL + k]                     = gv[k] * inv;
                out[(size_t)TT * KSEL + (size_t)r * KSEL + k] = (float)gi[k];
            }
            pinv_s = 1.f / (ssum + 1e-9f);
        }
        __syncthreads();
        atomicAdd(&g_pn[e], aff[e] * pinv_s);
        __syncthreads();
    }
}

// ---------------------------------------------------------------------------
__global__ void finalize_kernel(float* __restrict__ out) {
    __shared__ float red[EE];
    const int e = threadIdx.x;
    red[e] = g_cnt[e] * g_pn[e];
    __syncthreads();
    if (e == 0) {
        float s = 0.f;
        for (int i = 0; i < EE; i++) s += red[i];
        double loss = (double)s * 1e-4 * 64.0 / (8.0 * 16384.0) / 16384.0;
        out[(size_t)2 * TT * KSEL] = (float)loss;
    }
}

// ---------------------------------------------------------------------------
extern "C" void kernel_launch(void* const* d_in, const int* in_sizes, int n_in,
                              void* d_out, int out_size) {
    const float* x    = (const float*)d_in[0];
    const float* W    = (const float*)d_in[1];
    const float* bias = (const float*)d_in[2];
    float* out = (float*)d_out;

    static bool attr_done = false;
    if (!attr_done) {
        cudaFuncSetAttribute(router_kernel,
                             cudaFuncAttributeMaxDynamicSharedMemorySize, SMEM_TOTAL);
        attr_done = true;
    }

    prep_kernel<<<512, 256>>>(W);
    router_kernel<<<TT / BR, 256, SMEM_TOTAL>>>(x, bias, out);
    patch_kernel<<<512, 64>>>(x, W, bias, out);
    finalize_kernel<<<1, 64>>>(out);
}